// round 4
// baseline (speedup 1.0000x reference)
#include <cuda_runtime.h>

// FeatureFuser: out = sigmoid( last-write-wins(sampling_map, refined[k] over window_k) )
// B=8, TOP_K=4, C=32, H=W=256, GRID=4 (cell 64x64), WINDOW=3 cells (192x192, clipped).
//
// Per output pixel exactly one source is read: refined[b, k_win, c, h, w] where
// k_win = max k whose window contains (h,w), else sampling_map[b,c,h,w].
// Window x-bounds are multiples of 64 floats; each thread's 32 consecutive
// floats (32-aligned) therefore share a single winning k.
//
// regions arrive as int32 (JAX x64 disabled downcasts the int64 request).

#define B_    8
#define K_    4
#define C_    32
#define H_    256
#define W_    256
#define W4_   (W_/4)
#define V_    8           // float4s per thread (32 floats, one half-cell)

__device__ __forceinline__ float fast_sigmoid(float x) {
    float t;
    asm("tanh.approx.f32 %0, %1;" : "=f"(t) : "f"(0.5f * x));
    return fmaf(0.5f, t, 0.5f);
}

__device__ __forceinline__ void stcs4(float4* p, float4 v) {
    // Streaming store: output is never re-read; keep L2 for the source tensors.
    asm volatile("st.global.cs.v4.f32 [%0], {%1,%2,%3,%4};"
                 :: "l"(p), "f"(v.x), "f"(v.y), "f"(v.z), "f"(v.w) : "memory");
}

__global__ void __launch_bounds__(256, 8)
feature_fuser_kernel(const float* __restrict__ smap,
                     const float* __restrict__ rmap,
                     const int* __restrict__ regions,
                     float* __restrict__ out)
{
    int t = blockIdx.x * blockDim.x + threadIdx.x;
    int base4 = t * V_;                    // first float4 index (8 consecutive, same row/cell)
    int w4 = base4 & (W4_ - 1);
    int h  = (base4 >> 6) & (H_ - 1);
    int bc = base4 >> 14;                  // b*C + c (constant across the 8 float4s)
    int c  = bc & (C_ - 1);
    int b  = bc >> 5;
    int w  = w4 << 2;

    // Winning k: highest k whose window contains (h, w). Uniform for the whole group.
    int win = -1;
    #pragma unroll
    for (int k = K_ - 1; k >= 0; --k) {
        int ys = __ldg(&regions[(b * K_ + k) * 2 + 0]) << 6;
        int xs = __ldg(&regions[(b * K_ + k) * 2 + 1]) << 6;
        bool inside = (h >= ys) && (h < min(ys + 192, H_)) &&
                      (w >= xs) && (w < min(xs + 192, W_));
        if (win < 0 && inside) win = k;
    }

    long row = (long)h * W_;
    long off = (win >= 0)
        ? ((((long)b * K_ + win) * C_ + c) * (long)(H_ * W_)) + row
        : ((long)bc * (long)(H_ * W_)) + row;
    const float4* src = reinterpret_cast<const float4*>(
        (win >= 0 ? rmap : smap) + off) + w4;

    float4 v[V_];
    #pragma unroll
    for (int i = 0; i < V_; ++i) v[i] = __ldg(&src[i]);   // MLP=8

    #pragma unroll
    for (int i = 0; i < V_; ++i) {
        v[i].x = fast_sigmoid(v[i].x);
        v[i].y = fast_sigmoid(v[i].y);
        v[i].z = fast_sigmoid(v[i].z);
        v[i].w = fast_sigmoid(v[i].w);
    }

    float4* dst = reinterpret_cast<float4*>(out) + base4;
    #pragma unroll
    for (int i = 0; i < V_; ++i) stcs4(&dst[i], v[i]);
}

extern "C" void kernel_launch(void* const* d_in, const int* in_sizes, int n_in,
                              void* d_out, int out_size)
{
    const float* smap    = (const float*)d_in[0];
    const float* rmap    = (const float*)d_in[1];
    const int*   regions = (const int*)d_in[2];
    float*       out     = (float*)d_out;

    const int total4  = B_ * C_ * H_ * W_ / 4;       // 4,194,304 float4s
    const int threads = 256;
    const int blocks  = total4 / (threads * V_);     // 2048
    feature_fuser_kernel<<<blocks, threads>>>(smap, rmap, regions, out);
}

// round 5
// speedup vs baseline: 1.7802x; 1.7802x over previous
#include <cuda_runtime.h>

// FeatureFuser: out = sigmoid( last-write-wins(sampling_map, refined[k] over window_k) )
// B=8, TOP_K=4, C=32, H=W=256, GRID=4 (cell 64x64), WINDOW=3 cells (192x192, clipped).
//
// Per output pixel exactly one source is read: refined[b, k_win, c, h, w] where
// k_win = max k whose window contains (h,w), else sampling_map[b,c,h,w].
//
// Coalescing: iteration i of thread tid handles float4 index
//   blockBase + i*256 + tid  -> every LDG.128/STG.128 is a contiguous 512B warp access.
// A block covers 1024 float4s; one (b,c) plane is 16384 float4s (divisible), so
// b and c (and thus the region table) are uniform per block.
//
// regions arrive as int32 (JAX x64 disabled downcasts the int64 request).

#define B_    8
#define K_    4
#define C_    32
#define H_    256
#define W_    256
#define W4_   (W_/4)
#define V_    4           // float4s per thread, warp-strided

__device__ __forceinline__ float fast_sigmoid(float x) {
    float t;
    asm("tanh.approx.f32 %0, %1;" : "=f"(t) : "f"(0.5f * x));
    return fmaf(0.5f, t, 0.5f);
}

__global__ void __launch_bounds__(256)
feature_fuser_kernel(const float* __restrict__ smap,
                     const float* __restrict__ rmap,
                     const int* __restrict__ regions,
                     float* __restrict__ out)
{
    const int tid = threadIdx.x;
    const int blockBase = blockIdx.x * (256 * V_);   // float4 index
    const int bc = blockBase >> 14;                  // uniform per block
    const int c  = bc & (C_ - 1);
    const int b  = bc >> 5;

    // Hoist window bounds for this b (L1-resident, 8 ints).
    int ys[K_], ye[K_], xs[K_], xe[K_];
    #pragma unroll
    for (int k = 0; k < K_; ++k) {
        ys[k] = __ldg(&regions[(b * K_ + k) * 2 + 0]) << 6;
        xs[k] = __ldg(&regions[(b * K_ + k) * 2 + 1]) << 6;
        ye[k] = min(ys[k] + 192, H_);
        xe[k] = min(xs[k] + 192, W_);
    }

    const long plane = (long)(H_ * W_);
    const float* sbase = smap + (long)bc * plane;    // fallback plane
    const float* rbase = rmap + (((long)b * K_) * C_ + c) * plane;  // k=0 plane; +k*C_*plane per k

    float4 v[V_];
    #pragma unroll
    for (int i = 0; i < V_; ++i) {
        int idx = blockBase + i * 256 + tid;         // float4 index, lanes consecutive
        int w4  = idx & (W4_ - 1);
        int h   = (idx >> 6) & (H_ - 1);
        int w   = w4 << 2;

        int win = -1;
        #pragma unroll
        for (int k = K_ - 1; k >= 0; --k) {
            bool inside = (h >= ys[k]) & (h < ye[k]) & (w >= xs[k]) & (w < xe[k]);
            if (win < 0 && inside) win = k;
        }

        const float* base = (win >= 0) ? (rbase + (long)win * (C_ * plane)) : sbase;
        v[i] = __ldg(reinterpret_cast<const float4*>(base) + (long)h * W4_ + w4);
    }

    #pragma unroll
    for (int i = 0; i < V_; ++i) {
        v[i].x = fast_sigmoid(v[i].x);
        v[i].y = fast_sigmoid(v[i].y);
        v[i].z = fast_sigmoid(v[i].z);
        v[i].w = fast_sigmoid(v[i].w);
        reinterpret_cast<float4*>(out)[blockBase + i * 256 + tid] = v[i];
    }
}

extern "C" void kernel_launch(void* const* d_in, const int* in_sizes, int n_in,
                              void* d_out, int out_size)
{
    const float* smap    = (const float*)d_in[0];
    const float* rmap    = (const float*)d_in[1];
    const int*   regions = (const int*)d_in[2];
    float*       out     = (float*)d_out;

    const int total4  = B_ * C_ * H_ * W_ / 4;       // 4,194,304 float4s
    const int threads = 256;
    const int blocks  = total4 / (threads * V_);     // 4096
    feature_fuser_kernel<<<blocks, threads>>>(smap, rmap, regions, out);
}

// round 6
// speedup vs baseline: 1.8000x; 1.0111x over previous
#include <cuda_runtime.h>

// FeatureFuser: out = sigmoid( last-write-wins(sampling_map, refined[k] over window_k) )
// B=8, TOP_K=4, C=32, H=W=256, GRID=4 (cell 64x64), WINDOW=3 cells (192x192, clipped).
//
// Per output pixel exactly one source is read: refined[b, k_win, c, h, w] where
// k_win = max k whose window contains (h,w), else sampling_map[b,c,h,w].
//
// Warp-stride iteration: iteration i of thread tid handles float4 index
//   blockBase + i*256 + tid  -> every LDG.128/STG.128 is a contiguous 512B warp access.
// Within a thread, w4 = tid & 63 is invariant across iterations; only h varies
// (h = hbase + 4*i). So x-window predicates and w4-relative base pointers are
// hoisted; the inner k-scan is one unsigned range-check on h per k.
//
// Block covers 2048 float4s = 1/8 of a (b,c) plane -> b, c uniform per block.
// regions arrive as int32 (JAX x64 disabled downcasts the int64 request).

#define B_      8
#define K_      4
#define C_      32
#define H_      256
#define W_      256
#define W4_     (W_/4)
#define PLANE4  (H_*W_/4)      // 16384 float4s per (b,c) plane
#define V_      8              // float4s per thread, warp-strided

__device__ __forceinline__ float fast_sigmoid(float x) {
    float t;
    asm("tanh.approx.f32 %0, %1;" : "=f"(t) : "f"(0.5f * x));
    return fmaf(0.5f, t, 0.5f);
}

__global__ void __launch_bounds__(256)
feature_fuser_kernel(const float* __restrict__ smap,
                     const float* __restrict__ rmap,
                     const int* __restrict__ regions,
                     float* __restrict__ out)
{
    const int tid = threadIdx.x;
    const int w4  = tid & (W4_ - 1);                 // invariant per thread
    const int blockBase = blockIdx.x * (256 * V_);   // float4 index
    const int bc = blockBase >> 14;                  // uniform per block
    const int c  = bc & (C_ - 1);
    const int b  = bc >> 5;
    const int hbase = ((blockBase >> 6) & (H_ - 1)) + (tid >> 6);

    // Hoisted per-k state: y-range and x-predicate (x fixed per thread).
    int ys[K_]; unsigned ylen[K_]; bool xok[K_];
    #pragma unroll
    for (int k = 0; k < K_; ++k) {
        ys[k]   = __ldg(&regions[(b * K_ + k) * 2 + 0]) << 6;
        int xs4 =  __ldg(&regions[(b * K_ + k) * 2 + 1]) << 4;   // in float4 units
        ylen[k] = (unsigned)(min(ys[k] + 192, H_) - ys[k]);
        xok[k]  = (unsigned)(w4 - xs4) < (unsigned)(min(xs4 + 48, W4_) - xs4);
    }

    // Per-k source base pointers with w4 folded in.
    const float4* s4 = reinterpret_cast<const float4*>(smap) + (size_t)bc * PLANE4 + w4;
    const float4* r4 = reinterpret_cast<const float4*>(rmap)
                     + ((size_t)(b * K_) * C_ + c) * PLANE4 + w4;

    float4 v[V_];
    #pragma unroll
    for (int i = 0; i < V_; ++i) {
        int h = hbase + 4 * i;
        const float4* p = s4;
        #pragma unroll
        for (int k = 0; k < K_; ++k) {               // ascending: last write wins
            bool inside = xok[k] & ((unsigned)(h - ys[k]) < ylen[k]);
            const float4* pk = r4 + (size_t)k * (C_ * PLANE4);
            p = inside ? pk : p;
        }
        v[i] = __ldg(p + h * W4_);                   // MLP up to 8
    }

    float4* o4 = reinterpret_cast<float4*>(out) + blockBase + tid;
    #pragma unroll
    for (int i = 0; i < V_; ++i) {
        v[i].x = fast_sigmoid(v[i].x);
        v[i].y = fast_sigmoid(v[i].y);
        v[i].z = fast_sigmoid(v[i].z);
        v[i].w = fast_sigmoid(v[i].w);
        o4[i * 256] = v[i];
    }
}

extern "C" void kernel_launch(void* const* d_in, const int* in_sizes, int n_in,
                              void* d_out, int out_size)
{
    const float* smap    = (const float*)d_in[0];
    const float* rmap    = (const float*)d_in[1];
    const int*   regions = (const int*)d_in[2];
    float*       out     = (float*)d_out;

    const int total4  = B_ * C_ * H_ * W_ / 4;       // 4,194,304 float4s
    const int threads = 256;
    const int blocks  = total4 / (threads * V_);     // 2048
    feature_fuser_kernel<<<blocks, threads>>>(smap, rmap, regions, out);
}